// round 7
// baseline (speedup 1.0000x reference)
#include <cuda_runtime.h>
#include <cstdint>

#define ORD   24
#define TLEN  168
#define DD    512
#define SS    336
#define BB    256
#define CR2   26            // coef row stride in float2 (24 dup-coefs + bias + pad)
#define DQW   128           // d-quarter width per tile
#define NTILE (BB * 4)      // 1024 tiles = batch x d-quarter
#define GRIDB 296           // 148 SMs x 2 resident CTAs, single wave
#define NTHR  384           // 12 warps: warp w owns t in [14w, 14w+14)

__device__ int g_counter = 0;   // work-stealing counter (self-resets per launch)
__device__ int g_done    = 0;

// ---------------------------------------------------------------------------
// Packed fp32x2 FMA (sm_103a). PTX-only; ptxas won't auto-fuse.
// ---------------------------------------------------------------------------
__device__ __forceinline__ unsigned long long fma2(unsigned long long a,
                                                   unsigned long long x,
                                                   unsigned long long c) {
    unsigned long long d;
    asm("fma.rn.f32x2 %0, %1, %2, %3;" : "=l"(d) : "l"(a), "l"(x), "l"(c));
    return d;
}

// ---------------------------------------------------------------------------
// Fused kernel: per-CTA coef prologue (pre-duplicated {c,c} pairs) +
// register-blocked mixing mainloop over persistent work-stolen tiles.
//   Tile = (batch, d-quarter). 384 threads = 12 warps.
//   Warp w: t in [14w, 14w+14) as 2 passes of Mt=7.
//   Lane l: d-group l (4 floats) of the 128-wide quarter.
//   Thread tile: 7t x 4d, acc as 2x f32x2. Per 4-k block:
//     4 warp-wide ctx LDS.128 + 7x2 broadcast coef LDS.128 + 56 fma2 (0 movs).
// ---------------------------------------------------------------------------
__global__ void __launch_bounds__(NTHR, 2)
ar_fused_kernel(const float* __restrict__ x, const float* __restrict__ W,
                const float* __restrict__ bptr, float* __restrict__ out) {
    __shared__ __align__(16) float2 scoef[TLEN * CR2];  // 34.9 KB dup coef table
    __shared__ __align__(16) float  sctx[ORD * DQW];    // 12 KB ctx tile
    __shared__ int s_tile;

    const int tid  = threadIdx.x;
    const int warp = tid >> 5;
    const int lane = tid & 31;

    int tile = blockIdx.x;   // first tile pre-assigned (GRIDB < NTILE)

    // ---- stage ctx for the first tile (all threads) ----
    {
        const int batch = tile >> 2, dq = tile & 3;
        const float* xb = x + ((size_t)batch * SS + (SS - ORD)) * DD + dq * DQW;
        for (int v = tid; v < ORD * DQW / 4; v += NTHR) {
            const int j = v >> 5, c = v & 31;   // 32 float4 per k-row
            reinterpret_cast<float4*>(sctx)[v] =
                reinterpret_cast<const float4*>(xb + (size_t)j * DD)[c];
        }
    }

    // ---- coef prologue: thread j owns coefficient column j (24 = bias) ----
    if (tid < 25) {
        const int j = tid;
        float w[ORD];
#pragma unroll
        for (int i = 0; i < ORD; i++) w[i] = W[i];
        const float bias = bptr[0];

        float m[ORD];
#pragma unroll
        for (int i = 0; i < ORD; i++) m[i] = (j < ORD && i == j) ? 1.0f : 0.0f;

        for (int t = 0; t < TLEN; t++) {
            float p[ORD];
#pragma unroll
            for (int i = 0; i < ORD; i++) p[i] = w[i] * m[i];
#pragma unroll
            for (int k = 0; k < 12; k++) p[k] = p[2 * k] + p[2 * k + 1];
#pragma unroll
            for (int k = 0; k < 6; k++)  p[k] = p[2 * k] + p[2 * k + 1];
#pragma unroll
            for (int k = 0; k < 3; k++)  p[k] = p[2 * k] + p[2 * k + 1];
            float y = (p[0] + p[1]) + p[2];
            if (j == 24) y += bias;

            scoef[t * CR2 + j] = make_float2(y, y);   // pre-duplicated

#pragma unroll
            for (int i = 0; i < ORD - 1; i++) m[i] = m[i + 1];
            m[ORD - 1] = y;
        }
    }
    __syncthreads();

    // ---- persistent mainloop ----
    for (;;) {
        const int batch = tile >> 2, dq = tile & 3;
        float* ob = out + (size_t)batch * TLEN * DD + dq * DQW + lane * 4;

#pragma unroll 1
        for (int p = 0; p < 2; p++) {
            const int t0 = warp * 14 + p * 7;

            ulonglong2 acc[7];
#pragma unroll
            for (int i = 0; i < 7; i++) {
                const unsigned long long bb =
                    *reinterpret_cast<const unsigned long long*>(
                        &scoef[(t0 + i) * CR2 + 24]);
                acc[i].x = bb;
                acc[i].y = bb;
            }

#pragma unroll
            for (int kb = 0; kb < 6; kb++) {
                const int koff = kb * 4;
                // ctx fragment: 4 k-rows x 4 d (warp-wide LDS.128)
                const ulonglong2 b0 = *reinterpret_cast<const ulonglong2*>(
                    &sctx[(koff + 0) * DQW + lane * 4]);
                const ulonglong2 b1 = *reinterpret_cast<const ulonglong2*>(
                    &sctx[(koff + 1) * DQW + lane * 4]);
                const ulonglong2 b2 = *reinterpret_cast<const ulonglong2*>(
                    &sctx[(koff + 2) * DQW + lane * 4]);
                const ulonglong2 b3 = *reinterpret_cast<const ulonglong2*>(
                    &sctx[(koff + 3) * DQW + lane * 4]);

#pragma unroll
                for (int i = 0; i < 7; i++) {
                    // coef fragment: 4 dup-pairs for this t (2 broadcast LDS.128)
                    const ulonglong2 c01 = *reinterpret_cast<const ulonglong2*>(
                        &scoef[(t0 + i) * CR2 + koff]);
                    const ulonglong2 c23 = *reinterpret_cast<const ulonglong2*>(
                        &scoef[(t0 + i) * CR2 + koff + 2]);
                    acc[i].x = fma2(c01.x, b0.x, acc[i].x);
                    acc[i].y = fma2(c01.x, b0.y, acc[i].y);
                    acc[i].x = fma2(c01.y, b1.x, acc[i].x);
                    acc[i].y = fma2(c01.y, b1.y, acc[i].y);
                    acc[i].x = fma2(c23.x, b2.x, acc[i].x);
                    acc[i].y = fma2(c23.x, b2.y, acc[i].y);
                    acc[i].x = fma2(c23.y, b3.x, acc[i].x);
                    acc[i].y = fma2(c23.y, b3.y, acc[i].y);
                }
            }

#pragma unroll
            for (int i = 0; i < 7; i++) {
                union { ulonglong2 u; float4 f; } r;
                r.u = acc[i];
                __stcs(reinterpret_cast<float4*>(ob + (size_t)(t0 + i) * DD),
                       r.f);
            }
        }

        // ---- steal next tile ----
        __syncthreads();   // everyone done reading sctx
        if (tid == 0) s_tile = GRIDB + atomicAdd(&g_counter, 1);
        __syncthreads();
        tile = s_tile;
        if (tile >= NTILE) break;

        {   // stage ctx for the next tile
            const int nb = tile >> 2, ndq = tile & 3;
            const float* xb =
                x + ((size_t)nb * SS + (SS - ORD)) * DD + ndq * DQW;
            for (int v = tid; v < ORD * DQW / 4; v += NTHR) {
                const int j = v >> 5, c = v & 31;
                reinterpret_cast<float4*>(sctx)[v] =
                    reinterpret_cast<const float4*>(xb + (size_t)j * DD)[c];
            }
        }
        __syncthreads();
    }

    // ---- self-reset counters so each graph replay is identical ----
    if (tid == 0) {
        const int d = atomicAdd(&g_done, 1);
        if (d == GRIDB - 1) {
            atomicExch(&g_counter, 0);
            atomicExch(&g_done, 0);
        }
    }
}

// ---------------------------------------------------------------------------
extern "C" void kernel_launch(void* const* d_in, const int* in_sizes, int n_in,
                              void* d_out, int out_size) {
    const float* x = (const float*)d_in[0];   // [256, 336, 512] f32
    const float* W = (const float*)d_in[1];   // [24, 1] f32
    const float* b = (const float*)d_in[2];   // [1] f32
    float* out = (float*)d_out;               // [256, 168, 512] f32

    ar_fused_kernel<<<GRIDB, NTHR>>>(x, W, b, out);
}